// round 1
// baseline (speedup 1.0000x reference)
#include <cuda_runtime.h>
#include <math.h>

// Problem constants
#define NPTS 8192
#define KCEN 128
#define DDIM 512

// Scratch for norms (allocation-free per harness rules)
__device__ float g_xnorm[NPTS];
__device__ float g_cnorm[KCEN];

// ---------------------------------------------------------------------------
// Prepass: one warp per row, compute sum of squares for x rows and centroids.
// 8192 + 128 = 8320 warps -> 1040 blocks of 256 threads (8 warps).
// ---------------------------------------------------------------------------
__global__ __launch_bounds__(256) void norms_kernel(const float* __restrict__ x,
                                                    const float* __restrict__ cen) {
    int warp = (blockIdx.x * blockDim.x + threadIdx.x) >> 5;
    int lane = threadIdx.x & 31;

    const float* src;
    float* dst;
    if (warp < NPTS) {
        src = x + (size_t)warp * DDIM;
        dst = g_xnorm + warp;
    } else if (warp < NPTS + KCEN) {
        int r = warp - NPTS;
        src = cen + (size_t)r * DDIM;
        dst = g_cnorm + r;
    } else {
        return;
    }

    // 512 floats = 128 float4; 32 lanes -> 4 float4 each
    const float4* p = reinterpret_cast<const float4*>(src);
    float s = 0.0f;
#pragma unroll
    for (int i = 0; i < 4; i++) {
        float4 v = p[lane + i * 32];
        s = fmaf(v.x, v.x, s);
        s = fmaf(v.y, v.y, s);
        s = fmaf(v.z, v.z, s);
        s = fmaf(v.w, v.w, s);
    }
#pragma unroll
    for (int o = 16; o > 0; o >>= 1) s += __shfl_xor_sync(0xffffffffu, s, o);
    if (lane == 0) *dst = s;
}

// ---------------------------------------------------------------------------
// Main kernel: GEMM-like dot(x_n, c_k) with fused distance epilogue.
// CTA tile: 64 rows x 128 centroids, BK=16.
// 256 threads as 16(tx: col groups) x 16(ty: row groups); thread tile 4x8.
// ---------------------------------------------------------------------------
__global__ __launch_bounds__(256, 1) void dist_kernel(const float* __restrict__ x,
                                                      const float* __restrict__ cen,
                                                      float* __restrict__ out) {
    __shared__ float xs[16][64];    // [d][row]   4 KB
    __shared__ float cs[16][128];   // [d][col]   8 KB

    const int tid = threadIdx.x;
    const int tx = tid & 15;        // col group: cols tx*8 .. tx*8+7
    const int ty = tid >> 4;        // row group: rows ty*4 .. ty*4+3
    const int rowBase = blockIdx.x * 64;

    float acc[4][8];
#pragma unroll
    for (int i = 0; i < 4; i++)
#pragma unroll
        for (int j = 0; j < 8; j++) acc[i][j] = 0.0f;

    // Load mapping (global -> smem, transposed)
    const int xr = tid >> 2;          // 0..63 : row within x tile
    const int xc = (tid & 3) * 4;     // 0,4,8,12 : d offset (float4)
    const int cr = tid >> 2;          // 0..63 : centroid row (and +64)
    const int cc = (tid & 3) * 4;

    const float* xp  = x   + (size_t)(rowBase + xr) * DDIM + xc;
    const float* cp0 = cen + (size_t)cr * DDIM + cc;
    const float* cp1 = cen + (size_t)(cr + 64) * DDIM + cc;

    for (int k0 = 0; k0 < DDIM; k0 += 16) {
        float4 xv  = *reinterpret_cast<const float4*>(xp + k0);
        float4 cv0 = *reinterpret_cast<const float4*>(cp0 + k0);
        float4 cv1 = *reinterpret_cast<const float4*>(cp1 + k0);

        xs[xc + 0][xr] = xv.x;
        xs[xc + 1][xr] = xv.y;
        xs[xc + 2][xr] = xv.z;
        xs[xc + 3][xr] = xv.w;

        cs[cc + 0][cr] = cv0.x;
        cs[cc + 1][cr] = cv0.y;
        cs[cc + 2][cr] = cv0.z;
        cs[cc + 3][cr] = cv0.w;

        cs[cc + 0][cr + 64] = cv1.x;
        cs[cc + 1][cr + 64] = cv1.y;
        cs[cc + 2][cr + 64] = cv1.z;
        cs[cc + 3][cr + 64] = cv1.w;

        __syncthreads();

#pragma unroll
        for (int d = 0; d < 16; d++) {
            float4 a  = *reinterpret_cast<const float4*>(&xs[d][ty * 4]);
            float4 b0 = *reinterpret_cast<const float4*>(&cs[d][tx * 8]);
            float4 b1 = *reinterpret_cast<const float4*>(&cs[d][tx * 8 + 4]);
            float av[4] = {a.x, a.y, a.z, a.w};
            float bv[8] = {b0.x, b0.y, b0.z, b0.w, b1.x, b1.y, b1.z, b1.w};
#pragma unroll
            for (int i = 0; i < 4; i++)
#pragma unroll
                for (int j = 0; j < 8; j++)
                    acc[i][j] = fmaf(av[i], bv[j], acc[i][j]);
        }
        __syncthreads();
    }

    // Epilogue: dist = sqrt(max(||x||^2 + ||c||^2 - 2*dot, 0))
    float cn[8];
#pragma unroll
    for (int j = 0; j < 8; j++) cn[j] = g_cnorm[tx * 8 + j];

#pragma unroll
    for (int i = 0; i < 4; i++) {
        int n = rowBase + ty * 4 + i;
        float xn = g_xnorm[n];
        float res[8];
#pragma unroll
        for (int j = 0; j < 8; j++) {
            float v = xn + cn[j] - 2.0f * acc[i][j];
            res[j] = sqrtf(fmaxf(v, 0.0f));
        }
        float4* op = reinterpret_cast<float4*>(out + (size_t)n * KCEN + tx * 8);
        op[0] = make_float4(res[0], res[1], res[2], res[3]);
        op[1] = make_float4(res[4], res[5], res[6], res[7]);
    }
}

extern "C" void kernel_launch(void* const* d_in, const int* in_sizes, int n_in,
                              void* d_out, int out_size) {
    const float* x   = (const float*)d_in[0];
    const float* cen = (const float*)d_in[1];
    float* out = (float*)d_out;

    // 8320 row-norm warps / 8 warps per block = 1040 blocks
    norms_kernel<<<1040, 256>>>(x, cen);
    // 8192 / 64 rows per CTA = 128 CTAs
    dist_kernel<<<128, 256>>>(x, cen, out);
}

// round 4
// speedup vs baseline: 3.5579x; 3.5579x over previous
#include <cuda_runtime.h>
#include <cuda_bf16.h>
#include <cstdint>
#include <math.h>

#define NPTS 8192
#define KCEN 128
#define DDIM 512

// SMEM layout (dynamic):
//   [0)      sxn[64]  float   (row sq-norms, CTA-local rows)
//   [256)    scn[128] float   (centroid sq-norms)
//   [1024)   A: 64 rows  x 512 bf16, row stride 1040B  (66560 B)
//   [67584)  B: 128 rows x 512 bf16, row stride 1040B  (133120 B)
#define SB        1040u
#define SM_XN     0
#define SM_CN     256
#define SM_A      1024u
#define SM_B      67584u
#define SM_TOTAL  (67584u + 128u*SB)   // 200704

__device__ __forceinline__ uint32_t smem_u32_of(const void* p) {
    uint32_t a;
    asm("{ .reg .u64 t; cvta.to.shared.u64 t, %1; cvt.u32.u64 %0, t; }" : "=r"(a) : "l"(p));
    return a;
}

#define LDMATRIX_X4(r0, r1, r2, r3, addr) \
    asm volatile("ldmatrix.sync.aligned.m8n8.x4.shared.b16 {%0,%1,%2,%3}, [%4];" \
        : "=r"(r0), "=r"(r1), "=r"(r2), "=r"(r3) : "r"(addr))

#define MMA_BF16(c, a, b0, b1) \
    asm volatile("mma.sync.aligned.m16n8k16.row.col.f32.bf16.bf16.f32 " \
        "{%0,%1,%2,%3}, {%4,%5,%6,%7}, {%8,%9}, {%0,%1,%2,%3};" \
        : "+f"((c)[0]), "+f"((c)[1]), "+f"((c)[2]), "+f"((c)[3]) \
        : "r"((a)[0]), "r"((a)[1]), "r"((a)[2]), "r"((a)[3]), "r"(b0), "r"(b1))

// Load one fp32 row (512 floats) -> bf16 smem row (padded), return sq-norm via warp reduce.
__device__ __forceinline__ void load_row(const float* __restrict__ src, char* smem,
                                         uint32_t dst_off, float* norm_dst, int lane) {
    float s = 0.0f;
#pragma unroll
    for (int j = 0; j < 4; j++) {
        int c4 = lane + j * 32;                       // float4 index 0..127
        float4 v = *reinterpret_cast<const float4*>(src + c4 * 4);
        __nv_bfloat162 lo = __float22bfloat162_rn(make_float2(v.x, v.y));
        __nv_bfloat162 hi = __float22bfloat162_rn(make_float2(v.z, v.w));
        uint2 u;
        u.x = *reinterpret_cast<uint32_t*>(&lo);
        u.y = *reinterpret_cast<uint32_t*>(&hi);
        *reinterpret_cast<uint2*>(smem + dst_off + (uint32_t)c4 * 8u) = u;
        s = fmaf(v.x, v.x, fmaf(v.y, v.y, fmaf(v.z, v.z, fmaf(v.w, v.w, s))));
    }
#pragma unroll
    for (int o = 16; o > 0; o >>= 1) s += __shfl_xor_sync(0xffffffffu, s, o);
    if (lane == 0) *norm_dst = s;
}

__global__ __launch_bounds__(256, 1) void kmeans_dist_kernel(const float* __restrict__ x,
                                                             const float* __restrict__ cen,
                                                             float* __restrict__ out) {
    extern __shared__ char smem[];
    const uint32_t su = smem_u32_of(smem);
    const int tid  = threadIdx.x;
    const int wid  = tid >> 5;
    const int lane = tid & 31;
    const int rowBase = blockIdx.x * 64;

    float* sxn = reinterpret_cast<float*>(smem + SM_XN);
    float* scn = reinterpret_cast<float*>(smem + SM_CN);

    // ---- load + convert A (64 rows) and B (128 centroids), fused sq-norms ----
#pragma unroll
    for (int it = 0; it < 8; it++) {
        int r = wid + it * 8;                          // warp-per-row
        load_row(x + (size_t)(rowBase + r) * DDIM, smem, SM_A + (uint32_t)r * SB, &sxn[r], lane);
    }
#pragma unroll
    for (int it = 0; it < 16; it++) {
        int r = wid + it * 8;
        load_row(cen + (size_t)r * DDIM, smem, SM_B + (uint32_t)r * SB, &scn[r], lane);
    }
    __syncthreads();

    // ---- MMA phase: warp tile 32(m) x 32(n) ----
    const int wm = wid >> 2;                           // 0..1
    const int wn = wid & 3;                            // 0..3
    const int mbase = wm * 32;
    const int nbase = wn * 32;

    // ldmatrix source addresses (lane-dependent):
    //   lanes 0-15  -> rows base+lane,      k-bytes +0   (matrices 0,1: k 0-7)
    //   lanes 16-31 -> rows base+(lane-16), k-bytes +16  (matrices 2,3: k 8-15)
    const uint32_t koff = (uint32_t)(lane >> 4) * 16u;
    const int lrow = lane & 15;
    uint32_t aaddr[2], baddr[2];
#pragma unroll
    for (int f = 0; f < 2; f++) {
        aaddr[f] = su + SM_A + (uint32_t)(mbase + f * 16 + lrow) * SB + koff;
        baddr[f] = su + SM_B + (uint32_t)(nbase + f * 16 + lrow) * SB + koff;
    }

    float acc[2][4][4];
#pragma unroll
    for (int i = 0; i < 2; i++)
#pragma unroll
        for (int j = 0; j < 4; j++)
#pragma unroll
            for (int q = 0; q < 4; q++) acc[i][j][q] = 0.0f;

#pragma unroll 4
    for (int kk = 0; kk < 32; kk++) {
        const uint32_t kb = (uint32_t)kk * 32u;        // 16 bf16 = 32B per k-step
        uint32_t a[2][4];
        uint32_t br[2][4];
#pragma unroll
        for (int f = 0; f < 2; f++)
            LDMATRIX_X4(a[f][0], a[f][1], a[f][2], a[f][3], aaddr[f] + kb);
#pragma unroll
        for (int f = 0; f < 2; f++)
            LDMATRIX_X4(br[f][0], br[f][1], br[f][2], br[f][3], baddr[f] + kb);
        // B x4 regs: 0=(n0-7,k0-7) 1=(n8-15,k0-7) 2=(n0-7,k8-15) 3=(n8-15,k8-15)
#pragma unroll
        for (int fm = 0; fm < 2; fm++) {
#pragma unroll
            for (int fn = 0; fn < 4; fn++) {
                const int bi  = fn >> 1;
                const int sub = fn & 1;
                MMA_BF16(acc[fm][fn], a[fm], br[bi][sub], br[bi][sub + 2]);
            }
        }
    }

    // ---- epilogue: dist = sqrt(max(xn + cn - 2*dot, 0)) ----
    const int qrow = lane >> 2;                        // 0..7
    const int qcol = (lane & 3) * 2;                   // 0,2,4,6
#pragma unroll
    for (int fm = 0; fm < 2; fm++) {
        const int r0 = mbase + fm * 16 + qrow;         // rows r0 and r0+8
        const float xn0 = sxn[r0];
        const float xn1 = sxn[r0 + 8];
#pragma unroll
        for (int fn = 0; fn < 4; fn++) {
            const int c = nbase + fn * 8 + qcol;
            const float cn0 = scn[c];
            const float cn1 = scn[c + 1];
            float2 o0, o1;
            o0.x = sqrtf(fmaxf(xn0 + cn0 - 2.0f * acc[fm][fn][0], 0.0f));
            o0.y = sqrtf(fmaxf(xn0 + cn1 - 2.0f * acc[fm][fn][1], 0.0f));
            o1.x = sqrtf(fmaxf(xn1 + cn0 - 2.0f * acc[fm][fn][2], 0.0f));
            o1.y = sqrtf(fmaxf(xn1 + cn1 - 2.0f * acc[fm][fn][3], 0.0f));
            *reinterpret_cast<float2*>(out + (size_t)(rowBase + r0) * KCEN + c)     = o0;
            *reinterpret_cast<float2*>(out + (size_t)(rowBase + r0 + 8) * KCEN + c) = o1;
        }
    }
}

extern "C" void kernel_launch(void* const* d_in, const int* in_sizes, int n_in,
                              void* d_out, int out_size) {
    const float* x   = (const float*)d_in[0];
    const float* cen = (const float*)d_in[1];
    float* out = (float*)d_out;

    static bool attr_set = false;
    if (!attr_set) {
        cudaFuncSetAttribute(kmeans_dist_kernel,
                             cudaFuncAttributeMaxDynamicSharedMemorySize, SM_TOTAL);
        attr_set = true;
    }
    kmeans_dist_kernel<<<128, 256, SM_TOTAL>>>(x, cen, out);
}

// round 5
// speedup vs baseline: 4.4492x; 1.2505x over previous
#include <cuda_runtime.h>
#include <cuda_bf16.h>
#include <cstdint>
#include <math.h>

#define NPTS 8192
#define KCEN 128
#define DDIM 512

// Pre-converted centroids (bf16) + centroid sq-norms.
__device__ __nv_bfloat16 g_cb[KCEN * DDIM];   // 128 KB
__device__ float g_cnorm[KCEN];

// ---------------- SMEM layout (main kernel, dynamic) ----------------
// stride per row: 128 bf16 = 256B, padded to 272B (keeps ldmatrix conflict-free)
#define SB      272u
#define SM_XN   0u            // 64 floats
#define SM_CN   256u          // 128 floats
#define SM_A0   1024u         // 64*272  = 17408
#define SM_A1   18432u
#define SM_B0   35840u        // 128*272 = 34816
#define SM_B1   70656u
#define SM_TOTAL 105472u

__device__ __forceinline__ uint32_t smem_u32_of(const void* p) {
    uint32_t a;
    asm("{ .reg .u64 t; cvta.to.shared.u64 t, %1; cvt.u32.u64 %0, t; }" : "=r"(a) : "l"(p));
    return a;
}

#define LDMATRIX_X4(r0, r1, r2, r3, addr) \
    asm volatile("ldmatrix.sync.aligned.m8n8.x4.shared.b16 {%0,%1,%2,%3}, [%4];" \
        : "=r"(r0), "=r"(r1), "=r"(r2), "=r"(r3) : "r"(addr))

#define MMA_BF16(c, a, b0, b1) \
    asm volatile("mma.sync.aligned.m16n8k16.row.col.f32.bf16.bf16.f32 " \
        "{%0,%1,%2,%3}, {%4,%5,%6,%7}, {%8,%9}, {%0,%1,%2,%3};" \
        : "+f"((c)[0]), "+f"((c)[1]), "+f"((c)[2]), "+f"((c)[3]) \
        : "r"((a)[0]), "r"((a)[1]), "r"((a)[2]), "r"((a)[3]), "r"(b0), "r"(b1))

#define CP_ASYNC16(dst, src) \
    asm volatile("cp.async.cg.shared.global [%0], [%1], 16;" :: "r"(dst), "l"(src) : "memory")
#define CP_COMMIT() asm volatile("cp.async.commit_group;" ::: "memory")
#define CP_WAIT(n)  asm volatile("cp.async.wait_group %0;" :: "n"(n) : "memory")

// ---------------------------------------------------------------------------
// Prepass: centroids fp32 -> bf16 global + sq-norms. One warp per centroid.
// ---------------------------------------------------------------------------
__global__ __launch_bounds__(256) void cen_prep_kernel(const float* __restrict__ cen) {
    int warp = (blockIdx.x * 256 + threadIdx.x) >> 5;
    int lane = threadIdx.x & 31;
    if (warp >= KCEN) return;
    const float4* p = reinterpret_cast<const float4*>(cen + (size_t)warp * DDIM);
    float s = 0.0f;
#pragma unroll
    for (int j = 0; j < 4; j++) {
        float4 v = p[lane + j * 32];
        __nv_bfloat162 lo = __float22bfloat162_rn(make_float2(v.x, v.y));
        __nv_bfloat162 hi = __float22bfloat162_rn(make_float2(v.z, v.w));
        uint2 u;
        u.x = *reinterpret_cast<uint32_t*>(&lo);
        u.y = *reinterpret_cast<uint32_t*>(&hi);
        *reinterpret_cast<uint2*>(g_cb + (size_t)warp * DDIM + (lane + j * 32) * 4) = u;
        s = fmaf(v.x, v.x, fmaf(v.y, v.y, fmaf(v.z, v.z, fmaf(v.w, v.w, s))));
    }
#pragma unroll
    for (int o = 16; o > 0; o >>= 1) s += __shfl_xor_sync(0xffffffffu, s, o);
    if (lane == 0) g_cnorm[warp] = s;
}

// ---------------------------------------------------------------------------
// Main kernel helpers
// ---------------------------------------------------------------------------
// Stage A chunk (64 rows x 128 cols fp32) into registers. Warp w owns rows w+8i.
__device__ __forceinline__ void ldgA(const float* __restrict__ x, int rowBase, int chunk,
                                     int wid, int lane, float4 v[8]) {
#pragma unroll
    for (int i = 0; i < 8; i++) {
        int row = wid + i * 8;
        v[i] = *reinterpret_cast<const float4*>(
            x + (size_t)(rowBase + row) * DDIM + chunk * 128 + lane * 4);
    }
}

// Convert staged A regs -> bf16 smem buffer; fuse row sq-norm accumulation.
__device__ __forceinline__ void stsA(char* smem, uint32_t aoff, float* sxn,
                                     int wid, int lane, const float4 v[8]) {
#pragma unroll
    for (int i = 0; i < 8; i++) {
        int row = wid + i * 8;
        __nv_bfloat162 lo = __float22bfloat162_rn(make_float2(v[i].x, v[i].y));
        __nv_bfloat162 hi = __float22bfloat162_rn(make_float2(v[i].z, v[i].w));
        uint2 u;
        u.x = *reinterpret_cast<uint32_t*>(&lo);
        u.y = *reinterpret_cast<uint32_t*>(&hi);
        *reinterpret_cast<uint2*>(smem + aoff + (uint32_t)row * SB + (uint32_t)lane * 8u) = u;
        float s = fmaf(v[i].x, v[i].x, fmaf(v[i].y, v[i].y,
                  fmaf(v[i].z, v[i].z, v[i].w * v[i].w)));
#pragma unroll
        for (int o = 16; o > 0; o >>= 1) s += __shfl_xor_sync(0xffffffffu, s, o);
        if (lane == 0) sxn[row] += s;   // warp w owns row w+8i in every chunk: no race
    }
}

// Async-copy B chunk (128 rows x 128 cols bf16) from pre-converted global.
__device__ __forceinline__ void cpB(uint32_t su, uint32_t boff, int chunk, int tid) {
#pragma unroll
    for (int i = 0; i < 8; i++) {
        int unit = tid + i * 256;            // 2048 16B units
        int row = unit >> 4;
        int u   = unit & 15;
        const __nv_bfloat16* src = g_cb + (size_t)row * DDIM + chunk * 128 + u * 8;
        uint32_t dst = su + boff + (uint32_t)row * SB + (uint32_t)u * 16u;
        CP_ASYNC16(dst, src);
    }
}

// MMA over one K=128 chunk: warp tile 32x32, 8 k-steps of 16.
__device__ __forceinline__ void mma_chunk(uint32_t su, uint32_t aoff, uint32_t boff,
                                          int mbase, int nbase, int lane,
                                          float acc[2][4][4]) {
    const uint32_t koff = (uint32_t)(lane >> 4) * 16u;
    const int lrow = lane & 15;
    uint32_t aaddr[2], baddr[2];
#pragma unroll
    for (int f = 0; f < 2; f++) {
        aaddr[f] = su + aoff + (uint32_t)(mbase + f * 16 + lrow) * SB + koff;
        baddr[f] = su + boff + (uint32_t)(nbase + f * 16 + lrow) * SB + koff;
    }
#pragma unroll
    for (int kk = 0; kk < 8; kk++) {
        const uint32_t kb = (uint32_t)kk * 32u;
        uint32_t a[2][4], br[2][4];
#pragma unroll
        for (int f = 0; f < 2; f++)
            LDMATRIX_X4(a[f][0], a[f][1], a[f][2], a[f][3], aaddr[f] + kb);
#pragma unroll
        for (int f = 0; f < 2; f++)
            LDMATRIX_X4(br[f][0], br[f][1], br[f][2], br[f][3], baddr[f] + kb);
#pragma unroll
        for (int fm = 0; fm < 2; fm++)
#pragma unroll
            for (int fn = 0; fn < 4; fn++) {
                const int bi = fn >> 1, sub = fn & 1;
                MMA_BF16(acc[fm][fn], a[fm], br[bi][sub], br[bi][sub + 2]);
            }
    }
}

// ---------------------------------------------------------------------------
// Main kernel: 128 CTAs x 256 thr, CTA tile 64 rows x 128 centroids, K piped.
// ---------------------------------------------------------------------------
__global__ __launch_bounds__(256, 1) void kmeans_dist_kernel(const float* __restrict__ x,
                                                             float* __restrict__ out) {
    extern __shared__ char smem[];
    const uint32_t su = smem_u32_of(smem);
    const int tid  = threadIdx.x;
    const int wid  = tid >> 5;
    const int lane = tid & 31;
    const int rowBase = blockIdx.x * 64;

    float* sxn = reinterpret_cast<float*>(smem + SM_XN);
    float* scn = reinterpret_cast<float*>(smem + SM_CN);
    if (tid < 64)  sxn[tid] = 0.0f;
    if (tid < 128) scn[tid] = g_cnorm[tid];
    __syncthreads();

    const int mbase = (wid >> 2) * 32;
    const int nbase = (wid & 3) * 32;

    float acc[2][4][4];
#pragma unroll
    for (int i = 0; i < 2; i++)
#pragma unroll
        for (int j = 0; j < 4; j++)
#pragma unroll
            for (int q = 0; q < 4; q++) acc[i][j][q] = 0.0f;

    float4 st[8];

    // ---- prologue ----
    ldgA(x, rowBase, 0, wid, lane, st);
    cpB(su, SM_B0, 0, tid); CP_COMMIT();          // g0
    cpB(su, SM_B1, 1, tid); CP_COMMIT();          // g1
    stsA(smem, SM_A0, sxn, wid, lane, st);
    CP_WAIT(1); __syncthreads();                  // B0 + A0 ready

    // ---- chunk 0 ----
    ldgA(x, rowBase, 1, wid, lane, st);           // overlaps MMA
    mma_chunk(su, SM_A0, SM_B0, mbase, nbase, lane, acc);
    __syncthreads();                              // done reading A0/B0
    stsA(smem, SM_A1, sxn, wid, lane, st);
    cpB(su, SM_B0, 2, tid); CP_COMMIT();          // g2 (B0 free now)
    CP_WAIT(1); __syncthreads();                  // B1 + A1 ready

    // ---- chunk 1 ----
    ldgA(x, rowBase, 2, wid, lane, st);
    mma_chunk(su, SM_A1, SM_B1, mbase, nbase, lane, acc);
    __syncthreads();
    stsA(smem, SM_A0, sxn, wid, lane, st);
    cpB(su, SM_B1, 3, tid); CP_COMMIT();          // g3
    CP_WAIT(1); __syncthreads();                  // B0(c2) + A0(c2) ready

    // ---- chunk 2 ----
    ldgA(x, rowBase, 3, wid, lane, st);
    mma_chunk(su, SM_A0, SM_B0, mbase, nbase, lane, acc);
    __syncthreads();
    stsA(smem, SM_A1, sxn, wid, lane, st);
    CP_WAIT(0); __syncthreads();                  // B1(c3) + A1(c3) ready

    // ---- chunk 3 ----
    mma_chunk(su, SM_A1, SM_B1, mbase, nbase, lane, acc);

    // ---- epilogue: dist = sqrt(max(xn + cn - 2*dot, 0)) ----
    const int qrow = lane >> 2;
    const int qcol = (lane & 3) * 2;
#pragma unroll
    for (int fm = 0; fm < 2; fm++) {
        const int r0 = mbase + fm * 16 + qrow;
        const float xn0 = sxn[r0];
        const float xn1 = sxn[r0 + 8];
#pragma unroll
        for (int fn = 0; fn < 4; fn++) {
            const int c = nbase + fn * 8 + qcol;
            const float cn0 = scn[c];
            const float cn1 = scn[c + 1];
            float2 o0, o1;
            o0.x = sqrtf(fmaxf(xn0 + cn0 - 2.0f * acc[fm][fn][0], 0.0f));
            o0.y = sqrtf(fmaxf(xn0 + cn1 - 2.0f * acc[fm][fn][1], 0.0f));
            o1.x = sqrtf(fmaxf(xn1 + cn0 - 2.0f * acc[fm][fn][2], 0.0f));
            o1.y = sqrtf(fmaxf(xn1 + cn1 - 2.0f * acc[fm][fn][3], 0.0f));
            *reinterpret_cast<float2*>(out + (size_t)(rowBase + r0) * KCEN + c)     = o0;
            *reinterpret_cast<float2*>(out + (size_t)(rowBase + r0 + 8) * KCEN + c) = o1;
        }
    }
}

extern "C" void kernel_launch(void* const* d_in, const int* in_sizes, int n_in,
                              void* d_out, int out_size) {
    const float* x   = (const float*)d_in[0];
    const float* cen = (const float*)d_in[1];
    float* out = (float*)d_out;

    cudaFuncSetAttribute(kmeans_dist_kernel,
                         cudaFuncAttributeMaxDynamicSharedMemorySize, SM_TOTAL);

    cen_prep_kernel<<<16, 256>>>(cen);                       // 128 warps, one per centroid
    kmeans_dist_kernel<<<128, 256, SM_TOTAL>>>(x, out);      // 8192/64 rows
}